// round 15
// baseline (speedup 1.0000x reference)
#include <cuda_runtime.h>
#include <cuda_fp16.h>
#include <math.h>
#include <stdint.h>

#define NN 1024
#define BB 64
#define CC 64
#define HH 64
#define DD 16
#define CIN 128
#define BC 8192            // BB * CIN
#define KIO_G 49152        // 384*128
#define KIO_U 24576        // 384*64

// ---------------- scratch ----------------
__device__ float g_eg[NN * DD];
__device__ float g_eu[NN * DD];
__device__ float g_bg[NN * 128];
__device__ float g_bu[NN * 64];
__device__ float g_r[BB * NN * HH];

__device__ unsigned short g_Sgh[NN * NN];
__device__ unsigned short g_Suh[NN * NN];
__device__ unsigned short g_X0h[NN * BC];
__device__ unsigned short g_X1h[NN * BC];
__device__ unsigned short g_X2h[NN * BC];
__device__ unsigned short g_wgh[NN * KIO_G];
__device__ unsigned short g_wuh[NN * KIO_U];

// ---------------- helpers ----------------
__device__ __forceinline__ uint32_t smem_to_u32(const void* p) {
    uint32_t a;
    asm("{ .reg .u64 t; cvta.to.shared.u64 t, %1; cvt.u32.u64 %0, t; }" : "=r"(a) : "l"(p));
    return a;
}

#define CP_ASYNC16(dst, src) \
    asm volatile("cp.async.cg.shared.global [%0], [%1], 16;" :: "r"(dst), "l"(src))
#define CP_COMMIT()  asm volatile("cp.async.commit_group;" ::: "memory")
#define CP_WAIT0()   asm volatile("cp.async.wait_group 0;" ::: "memory")
#define CP_WAIT1()   asm volatile("cp.async.wait_group 1;" ::: "memory")

__device__ __forceinline__ void ldsm_x4(uint32_t& r0, uint32_t& r1, uint32_t& r2, uint32_t& r3,
                                        uint32_t addr) {
    asm volatile("ldmatrix.sync.aligned.m8n8.x4.shared.b16 {%0,%1,%2,%3}, [%4];"
                 : "=r"(r0), "=r"(r1), "=r"(r2), "=r"(r3) : "r"(addr));
}
__device__ __forceinline__ void ldsm_x4_t(uint32_t& r0, uint32_t& r1, uint32_t& r2, uint32_t& r3,
                                          uint32_t addr) {
    asm volatile("ldmatrix.sync.aligned.m8n8.x4.trans.shared.b16 {%0,%1,%2,%3}, [%4];"
                 : "=r"(r0), "=r"(r1), "=r"(r2), "=r"(r3) : "r"(addr));
}

__device__ __forceinline__ void mma16816(float* c, const uint32_t* a, const uint32_t* b) {
    asm volatile("mma.sync.aligned.m16n8k16.row.col.f32.f16.f16.f32 "
                 "{%0,%1,%2,%3}, {%4,%5,%6,%7}, {%8,%9}, {%0,%1,%2,%3};"
                 : "+f"(c[0]), "+f"(c[1]), "+f"(c[2]), "+f"(c[3])
                 : "r"(a[0]), "r"(a[1]), "r"(a[2]), "r"(a[3]), "r"(b[0]), "r"(b[1]));
}

__device__ __forceinline__ void f16split(float x, unsigned short& h, unsigned short& l) {
    __half hb = __float2half_rn(x);
    __half lb = __float2half_rn(x - __half2float(hb));
    h = *reinterpret_cast<unsigned short*>(&hb);
    l = *reinterpret_cast<unsigned short*>(&lb);
}

// ---------------- 1) e = LN(node_emb + time_emb), bias = e @ b_pool ----------------
__global__ void k_prep(const float* __restrict__ ne, const float* __restrict__ te,
                       const float* __restrict__ gw, const float* __restrict__ gbln,
                       const float* __restrict__ uw, const float* __restrict__ ubln,
                       const float* __restrict__ gate_b, const float* __restrict__ update_b)
{
    int n = blockIdx.x;
    int lane = threadIdx.x;
    int d = lane & 15;
    float v = ne[n * DD + d] + te[d];

    float s = v;
    #pragma unroll
    for (int off = 16; off > 0; off >>= 1) s += __shfl_xor_sync(0xffffffffu, s, off);
    float mean = s * (1.0f / 32.0f);
    float dv = v - mean;
    float q = dv * dv;
    #pragma unroll
    for (int off = 16; off > 0; off >>= 1) q += __shfl_xor_sync(0xffffffffu, q, off);
    float var = q * (1.0f / 32.0f);
    float inv = rsqrtf(var + 1e-12f);

    float eg = dv * inv * gw[d] + gbln[d];
    float eu = dv * inv * uw[d] + ubln[d];
    if (lane < 16) { g_eg[n * DD + d] = eg; g_eu[n * DD + d] = eu; }

    for (int o = lane; o < 128; o += 32) {
        float b = 0.f;
        #pragma unroll
        for (int dd = 0; dd < 16; dd++)
            b += __shfl_sync(0xffffffffu, eg, dd) * gate_b[dd * 128 + o];
        g_bg[n * 128 + o] = b;
    }
    for (int o = lane; o < 64; o += 32) {
        float b = 0.f;
        #pragma unroll
        for (int dd = 0; dd < 16; dd++)
            b += __shfl_sync(0xffffffffu, eu, dd) * update_b[dd * 64 + o];
        g_bu[n * 64 + o] = b;
    }
}

// ---------------- 2) S = softmax(e e^T), fp16; 16 rows/block, 512 threads ----------------
#define SUP_STRIDE 1032
#define SUP_SMEM (16 * SUP_STRIDE * 4)

__global__ void __launch_bounds__(512)
k_supports()
{
    extern __shared__ float eT[];
    const int which = blockIdx.y;
    const float* e = which ? g_eu : g_eg;
    unsigned short* Sh = which ? g_Suh : g_Sgh;
    const int tid = threadIdx.x;
    const int warp = tid >> 5, lane = tid & 31;
    const int n = (blockIdx.x << 4) + warp;

    #pragma unroll
    for (int i = 0; i < 32; i++) {
        int idx = tid + (i << 9);
        int m = idx >> 4, dd = idx & 15;
        eT[dd * SUP_STRIDE + m] = e[idx];
    }
    __syncthreads();

    float en[16];
    #pragma unroll
    for (int dd = 0; dd < 16; dd++) en[dd] = eT[dd * SUP_STRIDE + n];

    float lv[32];
    float mx = -1e30f;
    #pragma unroll
    for (int j = 0; j < 8; j++) {
        int m0 = (j << 7) + (lane << 2);
        float ax = 0.f, ay = 0.f, az = 0.f, aw = 0.f;
        #pragma unroll
        for (int dd = 0; dd < 16; dd++) {
            float4 v = *(const float4*)&eT[dd * SUP_STRIDE + m0];
            ax += en[dd] * v.x; ay += en[dd] * v.y;
            az += en[dd] * v.z; aw += en[dd] * v.w;
        }
        lv[j * 4 + 0] = ax; lv[j * 4 + 1] = ay;
        lv[j * 4 + 2] = az; lv[j * 4 + 3] = aw;
        mx = fmaxf(mx, fmaxf(fmaxf(ax, ay), fmaxf(az, aw)));
    }
    #pragma unroll
    for (int off = 16; off > 0; off >>= 1)
        mx = fmaxf(mx, __shfl_xor_sync(0xffffffffu, mx, off));

    float sum = 0.f;
    #pragma unroll
    for (int i = 0; i < 32; i++) { lv[i] = expf(lv[i] - mx); sum += lv[i]; }
    #pragma unroll
    for (int off = 16; off > 0; off >>= 1)
        sum += __shfl_xor_sync(0xffffffffu, sum, off);
    float invs = 1.0f / sum;

    #pragma unroll
    for (int j = 0; j < 8; j++) {
        int m0 = (j << 7) + (lane << 2);
        __half2 p0 = __floats2half2_rn(lv[j * 4 + 0] * invs, lv[j * 4 + 1] * invs);
        __half2 p1 = __floats2half2_rn(lv[j * 4 + 2] * invs, lv[j * 4 + 3] * invs);
        uint2 pk = { *reinterpret_cast<uint32_t*>(&p0), *reinterpret_cast<uint32_t*>(&p1) };
        *(uint2*)&Sh[n * NN + m0] = pk;
    }
}

// ---------------- 3) tensor-core wgen (combined gate+update) ----------------
__global__ void __launch_bounds__(256)
k_wgen_mma(const float* __restrict__ gate_W, const float* __restrict__ update_W)
{
    const int bx = blockIdx.x;
    const int which = bx >= (KIO_G / 512);
    const int KIO = which ? KIO_U : KIO_G;
    const float* Wp = which ? update_W : gate_W;
    unsigned short* wh = which ? g_wuh : g_wgh;
    const float* e = which ? g_eu : g_eg;
    const int kio0 = (which ? bx - KIO_G / 512 : bx) << 9;
    const int n0 = blockIdx.y << 6;

    __shared__ char sm[16384 + 2048 + 2048];
    const uint32_t su = smem_to_u32(sm);
    const int tid = threadIdx.x;
    const int wid = tid >> 5, lane = tid & 31;

    {
        float4 v = *(const float4*)&e[n0 * DD + tid * 4];
        ushort4 h4, l4;
        f16split(v.x, h4.x, l4.x); f16split(v.y, h4.y, l4.y);
        f16split(v.z, h4.z, l4.z); f16split(v.w, h4.w, l4.w);
        *(ushort4*)(sm + 16384 + tid * 8) = h4;
        *(ushort4*)(sm + 18432 + tid * 8) = l4;
    }
    #pragma unroll
    for (int i = 0; i < 8; i++) {
        int lin = tid + (i << 8);
        int r = lin >> 7;
        int cf4 = lin & 127;
        float4 v = *(const float4*)&Wp[(size_t)r * KIO + kio0 + cf4 * 4];
        __half2 p0 = __floats2half2_rn(v.x, v.y);
        __half2 p1 = __floats2half2_rn(v.z, v.w);
        uint2 pk = { *reinterpret_cast<uint32_t*>(&p0), *reinterpret_cast<uint32_t*>(&p1) };
        uint32_t cb = (uint32_t)(cf4 * 8);
        *(uint2*)(sm + r * 1024 + (cb ^ ((r & 7) << 4))) = pk;
    }
    __syncthreads();

    const int mw = wid & 3;
    const int nhalf = wid >> 2;
    const int g = lane >> 2, t4 = lane & 3;

    uint32_t a_h[4], a_l[4];
    {
        uint32_t ao = (uint32_t)((mw * 16 + (lane & 15)) * 32 + ((lane >> 4) << 4));
        ldsm_x4(a_h[0], a_h[1], a_h[2], a_h[3], su + 16384 + ao);
        ldsm_x4(a_l[0], a_l[1], a_l[2], a_l[3], su + 18432 + ao);
    }

    const int brow = (lane & 7) + (((lane >> 3) & 1) << 3);
    const uint32_t bxor = (uint32_t)((brow & 7) << 4);
    const uint32_t bgrp = (uint32_t)((lane >> 4) << 4);

    #pragma unroll
    for (int nt2 = 0; nt2 < 16; nt2++) {
        uint32_t b[2][2];
        uint32_t bo = (uint32_t)(brow * 1024) + ((uint32_t)(nhalf * 512 + nt2 * 32 + bgrp) ^ bxor);
        ldsm_x4_t(b[0][0], b[0][1], b[1][0], b[1][1], su + bo);
        #pragma unroll
        for (int t = 0; t < 2; t++) {
            float c[4] = {0.f, 0.f, 0.f, 0.f};
            mma16816(c, a_h, b[t]);
            mma16816(c, a_l, b[t]);
            int node = n0 + mw * 16 + g;
            int kio = kio0 + nhalf * 256 + nt2 * 16 + t * 8 + 2 * t4;
            __half2 p0 = __floats2half2_rn(c[0], c[1]);
            __half2 p1 = __floats2half2_rn(c[2], c[3]);
            *(uint32_t*)(wh + (size_t)node * KIO + kio)       = *reinterpret_cast<uint32_t*>(&p0);
            *(uint32_t*)(wh + (size_t)(node + 8) * KIO + kio) = *reinterpret_cast<uint32_t*>(&p1);
        }
    }
}

// ---------------- 4) build X0 = fp16(concat(x, state)) ----------------
__global__ void k_build_xin(const float* __restrict__ x, const float* __restrict__ state)
{
    int t = blockIdx.x * 256 + threadIdx.x;
    int n = t >> 11;
    int j = t & 2047;
    int b = j >> 5;
    int c = (j & 31) << 2;

    float4 v;
    if (c < 64) {
        v = *(const float4*)&x[b * (NN * CC) + n * CC + c];
    } else {
        v = *(const float4*)&state[b * (NN * HH) + n * HH + (c - 64)];
    }
    __half2 p0 = __floats2half2_rn(v.x, v.y);
    __half2 p1 = __floats2half2_rn(v.z, v.w);
    uint2 pk = { *reinterpret_cast<uint32_t*>(&p0), *reinterpret_cast<uint32_t*>(&p1) };
    *(uint2*)&g_X0h[n * BC + b * CIN + c] = pk;
}

// ---------------- 5) big GEMM: Y = A @ B  (B via trans-ldmatrix from [k][col]) ----------------
// mode 0: out = fp16(acc)
// mode 1: out = fp16(2*acc - X0join)     (Chebyshev: Y2 = 2*S@Y1 - X)
#define STAGE_BYTES 32768
#define TCG_SMEM 65536

__global__ void __launch_bounds__(256, 2)
k_mmagemm3(const unsigned short* __restrict__ Aarr,
           const unsigned short* __restrict__ Bx,
           unsigned short* __restrict__ Xout,
           int mode)
{
    extern __shared__ char smem[];
    const uint32_t smem_u = smem_to_u32(smem);
    const int tid = threadIdx.x;
    const int wid = tid >> 5;
    const int lane = tid & 31;
    const int rowA = blockIdx.y << 7;
    const int bcol = blockIdx.x << 7;
    const int wm = wid & 1;
    const int wn = wid >> 1;

    float acc[4][4][4];
    #pragma unroll
    for (int i = 0; i < 4; i++)
        #pragma unroll
        for (int j = 0; j < 4; j++)
            #pragma unroll
            for (int q = 0; q < 4; q++) acc[i][j][q] = 0.f;

    const int arow = wm * 64 + (lane & 15);
    const int axor = (arow & 7) << 4;
    const int agco = (lane >> 4) << 4;
    const int bkrow = (lane & 7) + (((lane >> 3) & 1) << 3);
    const uint32_t bxor2 = (uint32_t)((lane & 7) << 4);
    const uint32_t bgrp = (uint32_t)((lane >> 4) << 4);

    auto load_stage = [&](int buf, int kk) {
        uint32_t dst0 = smem_u + buf * STAGE_BYTES;
        #pragma unroll
        for (int i = 0; i < 8; i++) {
            int lin = tid + (i << 8);
            if (lin < 1024) {
                int r = lin >> 3;
                int cb = (lin & 7) << 4;
                const char* src = (const char*)(Aarr + (size_t)(rowA + r) * NN + kk) + cb;
                CP_ASYNC16(dst0 + r * 128 + (cb ^ ((r & 7) << 4)), src);
            } else {
                int idx = lin - 1024;
                int kr = idx >> 4;
                int cb = (idx & 15) << 4;
                const char* src = (const char*)(Bx + (size_t)(kk + kr) * BC + bcol) + cb;
                CP_ASYNC16(dst0 + 16384 + kr * 256 + (cb ^ ((kr & 7) << 4)), src);
            }
        }
        CP_COMMIT();
    };

    load_stage(0, 0);

    #pragma unroll 1
    for (int s = 0; s < 16; s++) {
        const int buf = s & 1;
        CP_WAIT0();
        __syncthreads();
        if (s + 1 < 16) load_stage(1 - buf, (s + 1) << 6);

        const uint32_t sb = smem_u + buf * STAGE_BYTES;
        #pragma unroll
        for (int ks = 0; ks < 4; ks++) {
            const int c = ks << 5;
            uint32_t ah[4][4], bh[4][2];
            #pragma unroll
            for (int mt = 0; mt < 4; mt++) {
                uint32_t ao = (uint32_t)((arow + mt * 16) * 128) + (uint32_t)((c + agco) ^ axor);
                ldsm_x4(ah[mt][0], ah[mt][1], ah[mt][2], ah[mt][3], sb + ao);
            }
            #pragma unroll
            for (int nb = 0; nb < 2; nb++) {
                uint32_t bo = (uint32_t)((ks * 16 + bkrow) * 256)
                            + ((uint32_t)(wn * 64 + nb * 32 + bgrp) ^ bxor2);
                ldsm_x4_t(bh[2 * nb][0], bh[2 * nb][1], bh[2 * nb + 1][0], bh[2 * nb + 1][1],
                          sb + 16384 + bo);
            }
            #pragma unroll
            for (int mt = 0; mt < 4; mt++)
                #pragma unroll
                for (int nt = 0; nt < 4; nt++)
                    mma16816(acc[mt][nt], ah[mt], bh[nt]);
        }
        __syncthreads();
    }

    const int g = lane >> 2, t4 = lane & 3;
    if (mode == 0) {
        #pragma unroll
        for (int mt = 0; mt < 4; mt++)
            #pragma unroll
            for (int nt = 0; nt < 4; nt++) {
                int m0 = wm * 64 + mt * 16 + g;
                int n0c = wn * 32 + nt * 8 + 2 * t4;
                #pragma unroll
                for (int half = 0; half < 2; half++) {
                    int m = m0 + half * 8;
                    __half2 p = __floats2half2_rn(acc[mt][nt][2 * half],
                                                  acc[mt][nt][2 * half + 1]);
                    *(uint32_t*)(Xout + (size_t)(rowA + m) * BC + bcol + n0c) =
                        *reinterpret_cast<uint32_t*>(&p);
                }
            }
    } else {
        #pragma unroll
        for (int mt = 0; mt < 4; mt++)
            #pragma unroll
            for (int nt = 0; nt < 4; nt++) {
                int m0 = wm * 64 + mt * 16 + g;
                int n0c = wn * 32 + nt * 8 + 2 * t4;
                #pragma unroll
                for (int half = 0; half < 2; half++) {
                    int m = m0 + half * 8;
                    size_t o = (size_t)(rowA + m) * BC + bcol + n0c;
                    uint32_t dpk = *(const uint32_t*)&g_X0h[o];
                    __half2 dh = *reinterpret_cast<__half2*>(&dpk);
                    float d0 = __low2float(dh), d1 = __high2float(dh);
                    __half2 p = __floats2half2_rn(2.0f * acc[mt][nt][2 * half]     - d0,
                                                  2.0f * acc[mt][nt][2 * half + 1] - d1);
                    *(uint32_t*)(Xout + o) = *reinterpret_cast<uint32_t*>(&p);
                }
            }
    }
}

// ---------------- 6) node GEMM gate (1-term, double-buffered) ----------------
#define GATE_STAGE 24576
#define GATE_SMEM 49152

__global__ void __launch_bounds__(256)
k_tc_gate(const float* __restrict__ state)
{
    extern __shared__ char sm[];
    const uint32_t su = smem_to_u32(sm);
    const int n = blockIdx.x;
    const int tid = threadIdx.x;
    const int wid = tid >> 5, lane = tid & 31;
    const int wm = wid & 1, wn = wid >> 1;

    const unsigned short* xh[3] = { g_X0h + (size_t)n * BC, g_X1h + (size_t)n * BC, g_X2h + (size_t)n * BC };
    const unsigned short* wh = g_wgh + (size_t)n * KIO_G;

    float acc[2][4][4];
    #pragma unroll
    for (int i = 0; i < 2; i++)
        #pragma unroll
        for (int j = 0; j < 4; j++)
            #pragma unroll
            for (int q = 0; q < 4; q++) acc[i][j][q] = 0.f;

    const int arow = wm * 32 + (lane & 15);
    const int axor = (arow & 7) << 4;
    const int agco = (lane >> 4) << 4;
    const int brow = (lane & 7) + (((lane >> 3) & 1) << 3);
    const int bxor = (lane & 7) << 4;
    const int bgrp = (lane >> 4) << 4;

    auto load_stage = [&](int buf, int q) {
        const int t = q >> 1;
        const int c0 = (q & 1) << 6;
        uint32_t b0 = su + buf * GATE_STAGE;
        #pragma unroll
        for (int i = 0; i < 2; i++) {
            int lin = tid + (i << 8);
            int r = lin >> 3;
            int cb = (lin & 7) << 4;
            CP_ASYNC16(b0 + r * 128 + (cb ^ ((r & 7) << 4)),
                       (const char*)(xh[t] + r * 128 + c0) + cb);
        }
        #pragma unroll
        for (int i = 0; i < 4; i++) {
            int lin = tid + (i << 8);
            int kr = lin >> 4;
            int cb = (lin & 15) << 4;
            CP_ASYNC16(b0 + 8192 + kr * 256 + (cb ^ ((kr & 7) << 4)),
                       (const char*)(wh + (size_t)(q * 64 + kr) * 128) + cb);
        }
        CP_COMMIT();
    };

    load_stage(0, 0);

    #pragma unroll 1
    for (int q = 0; q < 6; q++) {
        const int buf = q & 1;
        if (q + 1 < 6) { load_stage(1 - buf, q + 1); CP_WAIT1(); }
        else           { CP_WAIT0(); }
        __syncthreads();

        const uint32_t sb = su + buf * GATE_STAGE;
        #pragma unroll
        for (int ks = 0; ks < 4; ks++) {
            const int c = ks << 5;
            uint32_t ah[2][4], bh[4][2];
            #pragma unroll
            for (int mt = 0; mt < 2; mt++) {
                uint32_t ao = (uint32_t)((arow + mt * 16) * 128) + (uint32_t)((c + agco) ^ axor);
                ldsm_x4(ah[mt][0], ah[mt][1], ah[mt][2], ah[mt][3], sb + ao);
            }
            #pragma unroll
            for (int nb = 0; nb < 2; nb++) {
                uint32_t bo = (uint32_t)((ks * 16 + brow) * 256)
                            + (uint32_t)((wn * 64 + nb * 32 + bgrp) ^ bxor);
                ldsm_x4_t(bh[2 * nb][0], bh[2 * nb][1], bh[2 * nb + 1][0], bh[2 * nb + 1][1],
                          sb + 8192 + bo);
            }
            #pragma unroll
            for (int mt = 0; mt < 2; mt++)
                #pragma unroll
                for (int nt = 0; nt < 4; nt++)
                    mma16816(acc[mt][nt], ah[mt], bh[nt]);
        }
        __syncthreads();
    }

    const int g = lane >> 2, t4 = lane & 3;
    #pragma unroll
    for (int mt = 0; mt < 2; mt++) {
        int b0 = wm * 32 + mt * 16 + g;
        #pragma unroll
        for (int nt = 0; nt < 4; nt++) {
            int o = wn * 32 + nt * 8 + 2 * t4;
            float bi0 = g_bg[n * 128 + o];
            float bi1 = g_bg[n * 128 + o + 1];
            #pragma unroll
            for (int half = 0; half < 2; half++) {
                int b = b0 + half * 8;
                float v0 = acc[mt][nt][2 * half]     + bi0;
                float v1 = acc[mt][nt][2 * half + 1] + bi1;
                float s0 = 1.0f / (1.0f + expf(-v0));
                float s1 = 1.0f / (1.0f + expf(-v1));
                if (o < 64) {
                    int sidx = b * (NN * HH) + n * HH + o;
                    __half2 p = __floats2half2_rn(s0 * state[sidx], s1 * state[sidx + 1]);
                    *(uint32_t*)&g_X0h[n * BC + b * CIN + 64 + o] =
                        *reinterpret_cast<uint32_t*>(&p);
                } else {
                    int base = b * (NN * HH) + n * HH + (o - 64);
                    g_r[base] = s0; g_r[base + 1] = s1;
                }
            }
        }
    }
}

// ---------------- 7) node GEMM update (1-term, double-buffered) ----------------
#define UPD_STAGE 16384

__global__ void __launch_bounds__(128)
k_tc_upd(const float* __restrict__ state, float* __restrict__ dout)
{
    __shared__ char sm[2 * UPD_STAGE];
    const uint32_t su = smem_to_u32(sm);
    const int n = blockIdx.x;
    const int tid = threadIdx.x;
    const int wid = tid >> 5, lane = tid & 31;
    const int wm = wid & 1, wn = wid >> 1;

    const unsigned short* xh[3] = { g_X0h + (size_t)n * BC, g_X1h + (size_t)n * BC, g_X2h + (size_t)n * BC };
    const unsigned short* wh = g_wuh + (size_t)n * KIO_U;

    float acc[2][4][4];
    #pragma unroll
    for (int i = 0; i < 2; i++)
        #pragma unroll
        for (int j = 0; j < 4; j++)
            #pragma unroll
            for (int q = 0; q < 4; q++) acc[i][j][q] = 0.f;

    const int arow = wm * 32 + (lane & 15);
    const int axor = (arow & 7) << 4;
    const int agco = (lane >> 4) << 4;
    const int brow = (lane & 7) + (((lane >> 3) & 1) << 3);
    const int bxor = (lane & 7) << 4;
    const int bgrp = (lane >> 4) << 4;

    auto load_stage = [&](int buf, int q) {
        const int t = q >> 1;
        const int c0 = (q & 1) << 6;
        uint32_t b0 = su + buf * UPD_STAGE;
        #pragma unroll
        for (int i = 0; i < 4; i++) {
            int lin = tid + (i << 7);
            int r = lin >> 3;
            int cb = (lin & 7) << 4;
            CP_ASYNC16(b0 + r * 128 + (cb ^ ((r & 7) << 4)),
                       (const char*)(xh[t] + r * 128 + c0) + cb);
        }
        #pragma unroll
        for (int i = 0; i < 4; i++) {
            int lin = tid + (i << 7);
            int kr = lin >> 3;
            int cb = (lin & 7) << 4;
            CP_ASYNC16(b0 + 8192 + kr * 128 + (cb ^ ((kr & 7) << 4)),
                       (const char*)(wh + (size_t)(q * 64 + kr) * 64) + cb);
        }
        CP_COMMIT();
    };

    load_stage(0, 0);

    #pragma unroll 1
    for (int q = 0; q < 6; q++) {
        const int buf = q & 1;
        if (q + 1 < 6) { load_stage(1 - buf, q + 1); CP_WAIT1(); }
        else           { CP_WAIT0(); }
        __syncthreads();

        const uint32_t sb = su + buf * UPD_STAGE;
        #pragma unroll
        for (int ks = 0; ks < 4; ks++) {
            const int c = ks << 5;
            uint32_t ah[2][4], bh[4][2];
            #pragma unroll
            for (int mt = 0; mt < 2; mt++) {
                uint32_t ao = (uint32_t)((arow + mt * 16) * 128) + (uint32_t)((c + agco) ^ axor);
                ldsm_x4(ah[mt][0], ah[mt][1], ah[mt][2], ah[mt][3], sb + ao);
            }
            #pragma unroll
            for (int nb = 0; nb < 2; nb++) {
                uint32_t bo = (uint32_t)((ks * 16 + brow) * 128)
                            + (uint32_t)((wn * 64 + nb * 32 + bgrp) ^ bxor);
                ldsm_x4_t(bh[2 * nb][0], bh[2 * nb][1], bh[2 * nb + 1][0], bh[2 * nb + 1][1],
                          sb + 8192 + bo);
            }
            #pragma unroll
            for (int mt = 0; mt < 2; mt++)
                #pragma unroll
                for (int nt = 0; nt < 4; nt++)
                    mma16816(acc[mt][nt], ah[mt], bh[nt]);
        }
        __syncthreads();
    }

    const int g = lane >> 2, t4 = lane & 3;
    #pragma unroll
    for (int mt = 0; mt < 2; mt++) {
        int b0 = wm * 32 + mt * 16 + g;
        #pragma unroll
        for (int nt = 0; nt < 4; nt++) {
            int o = wn * 32 + nt * 8 + 2 * t4;
            float bi0 = g_bu[n * 64 + o];
            float bi1 = g_bu[n * 64 + o + 1];
            #pragma unroll
            for (int half = 0; half < 2; half++) {
                int b = b0 + half * 8;
                float hc0 = tanhf(acc[mt][nt][2 * half]     + bi0);
                float hc1 = tanhf(acc[mt][nt][2 * half + 1] + bi1);
                int idx = b * (NN * HH) + n * HH + o;
                float r0 = g_r[idx],     st0 = state[idx];
                float r1 = g_r[idx + 1], st1 = state[idx + 1];
                dout[idx]     = r0 * st0 + (1.0f - r0) * hc0;
                dout[idx + 1] = r1 * st1 + (1.0f - r1) * hc1;
            }
        }
    }
}

// ---------------- launch ----------------
extern "C" void kernel_launch(void* const* d_in, const int* in_sizes, int n_in,
                              void* d_out, int out_size)
{
    const float* x         = (const float*)d_in[0];
    const float* state     = (const float*)d_in[2];
    const float* node_emb  = (const float*)d_in[3];
    const float* time_emb  = (const float*)d_in[5];
    const float* gate_W    = (const float*)d_in[6];
    const float* gate_b    = (const float*)d_in[7];
    const float* gate_lnw  = (const float*)d_in[8];
    const float* gate_lnb  = (const float*)d_in[9];
    const float* update_W  = (const float*)d_in[10];
    const float* update_b  = (const float*)d_in[11];
    const float* update_lnw= (const float*)d_in[12];
    const float* update_lnb= (const float*)d_in[13];
    float* out = (float*)d_out;

    unsigned short *Sgh, *Suh, *X0h, *X1h, *X2h;
    cudaGetSymbolAddress((void**)&Sgh, g_Sgh);
    cudaGetSymbolAddress((void**)&Suh, g_Suh);
    cudaGetSymbolAddress((void**)&X0h, g_X0h);
    cudaGetSymbolAddress((void**)&X1h, g_X1h);
    cudaGetSymbolAddress((void**)&X2h, g_X2h);

    static cudaStream_t sB = nullptr, sW = nullptr;
    static cudaEvent_t evRoot = nullptr, evPrep = nullptr, evB = nullptr, evW = nullptr;
    if (!sB) {
        cudaStreamCreateWithFlags(&sB, cudaStreamNonBlocking);
        cudaStreamCreateWithFlags(&sW, cudaStreamNonBlocking);
        cudaEventCreateWithFlags(&evRoot, cudaEventDisableTiming);
        cudaEventCreateWithFlags(&evPrep, cudaEventDisableTiming);
        cudaEventCreateWithFlags(&evB, cudaEventDisableTiming);
        cudaEventCreateWithFlags(&evW, cudaEventDisableTiming);
        cudaFuncSetAttribute(k_mmagemm3, cudaFuncAttributeMaxDynamicSharedMemorySize, TCG_SMEM);
        cudaFuncSetAttribute(k_tc_gate, cudaFuncAttributeMaxDynamicSharedMemorySize, GATE_SMEM);
        cudaFuncSetAttribute(k_supports, cudaFuncAttributeMaxDynamicSharedMemorySize, SUP_SMEM);
    }

    cudaEventRecord(evRoot, 0);

    // branch B: build X0 (no deps)
    cudaStreamWaitEvent(sB, evRoot, 0);
    k_build_xin<<<(NN * BC / 4) / 256, 256, 0, sB>>>(x, state);
    cudaEventRecord(evB, sB);

    // main: prep
    k_prep<<<NN, 32>>>(node_emb, time_emb, gate_lnw, gate_lnb, update_lnw, update_lnb,
                       gate_b, update_b);
    cudaEventRecord(evPrep, 0);

    // branch W: per-node weights (needs e)
    cudaStreamWaitEvent(sW, evPrep, 0);
    k_wgen_mma<<<dim3(KIO_G / 512 + KIO_U / 512, NN / 64), 256, 0, sW>>>(gate_W, update_W);
    cudaEventRecord(evW, sW);

    // main: supports
    k_supports<<<dim3(NN / 16, 2), 512, SUP_SMEM>>>();

    dim3 gg(BC / 128, NN / 128);

    // ---- gate magcn: Y1 = Sg@X0; Y2 = 2*Sg@Y1 - X0 ----
    cudaStreamWaitEvent(0, evB, 0);
    k_mmagemm3<<<gg, 256, TCG_SMEM>>>(Sgh, X0h, X1h, 0);
    k_mmagemm3<<<gg, 256, TCG_SMEM>>>(Sgh, X1h, X2h, 1);
    cudaStreamWaitEvent(0, evW, 0);
    k_tc_gate<<<NN, 256, GATE_SMEM>>>(state);   // z*state -> X0 state-half; r -> g_r

    // ---- update magcn ----
    k_mmagemm3<<<gg, 256, TCG_SMEM>>>(Suh, X0h, X1h, 0);
    k_mmagemm3<<<gg, 256, TCG_SMEM>>>(Suh, X1h, X2h, 1);
    k_tc_upd<<<NN, 128>>>(state, out);
}

// round 16
// speedup vs baseline: 1.0708x; 1.0708x over previous
#include <cuda_runtime.h>
#include <cuda_fp16.h>
#include <math.h>
#include <stdint.h>

#define NN 1024
#define BB 64
#define CC 64
#define HH 64
#define DD 16
#define CIN 128
#define BC 8192            // BB * CIN
#define KIO_G 49152        // 384*128
#define KIO_U 24576        // 384*64

// ---------------- scratch ----------------
__device__ float g_eg[NN * DD];
__device__ float g_eu[NN * DD];
__device__ float g_bg[NN * 128];
__device__ float g_bu[NN * 64];
__device__ float g_r[BB * NN * HH];

__device__ unsigned short g_Sgh[NN * NN];
__device__ unsigned short g_Suh[NN * NN];
__device__ unsigned short g_T2g[NN * NN];   // 2*Sg^2 - I (fp16)
__device__ unsigned short g_T2u[NN * NN];   // 2*Su^2 - I (fp16)
__device__ unsigned short g_X0h[NN * BC];
__device__ unsigned short g_X1h[NN * BC];
__device__ unsigned short g_X2h[NN * BC];
__device__ unsigned short g_wgh[NN * KIO_G];
__device__ unsigned short g_wuh[NN * KIO_U];

// ---------------- helpers ----------------
__device__ __forceinline__ uint32_t smem_to_u32(const void* p) {
    uint32_t a;
    asm("{ .reg .u64 t; cvta.to.shared.u64 t, %1; cvt.u32.u64 %0, t; }" : "=r"(a) : "l"(p));
    return a;
}

#define CP_ASYNC16(dst, src) \
    asm volatile("cp.async.cg.shared.global [%0], [%1], 16;" :: "r"(dst), "l"(src))
#define CP_COMMIT()  asm volatile("cp.async.commit_group;" ::: "memory")
#define CP_WAIT0()   asm volatile("cp.async.wait_group 0;" ::: "memory")
#define CP_WAIT1()   asm volatile("cp.async.wait_group 1;" ::: "memory")

__device__ __forceinline__ void ldsm_x4(uint32_t& r0, uint32_t& r1, uint32_t& r2, uint32_t& r3,
                                        uint32_t addr) {
    asm volatile("ldmatrix.sync.aligned.m8n8.x4.shared.b16 {%0,%1,%2,%3}, [%4];"
                 : "=r"(r0), "=r"(r1), "=r"(r2), "=r"(r3) : "r"(addr));
}
__device__ __forceinline__ void ldsm_x4_t(uint32_t& r0, uint32_t& r1, uint32_t& r2, uint32_t& r3,
                                          uint32_t addr) {
    asm volatile("ldmatrix.sync.aligned.m8n8.x4.trans.shared.b16 {%0,%1,%2,%3}, [%4];"
                 : "=r"(r0), "=r"(r1), "=r"(r2), "=r"(r3) : "r"(addr));
}

__device__ __forceinline__ void mma16816(float* c, const uint32_t* a, const uint32_t* b) {
    asm volatile("mma.sync.aligned.m16n8k16.row.col.f32.f16.f16.f32 "
                 "{%0,%1,%2,%3}, {%4,%5,%6,%7}, {%8,%9}, {%0,%1,%2,%3};"
                 : "+f"(c[0]), "+f"(c[1]), "+f"(c[2]), "+f"(c[3])
                 : "r"(a[0]), "r"(a[1]), "r"(a[2]), "r"(a[3]), "r"(b[0]), "r"(b[1]));
}

__device__ __forceinline__ void f16split(float x, unsigned short& h, unsigned short& l) {
    __half hb = __float2half_rn(x);
    __half lb = __float2half_rn(x - __half2float(hb));
    h = *reinterpret_cast<unsigned short*>(&hb);
    l = *reinterpret_cast<unsigned short*>(&lb);
}

// ---------------- 1) e = LN(node_emb + time_emb), bias = e @ b_pool; 8 warps/block ----------------
__global__ void __launch_bounds__(256)
k_prep(const float* __restrict__ ne, const float* __restrict__ te,
       const float* __restrict__ gw, const float* __restrict__ gbln,
       const float* __restrict__ uw, const float* __restrict__ ubln,
       const float* __restrict__ gate_b, const float* __restrict__ update_b)
{
    int n = (blockIdx.x << 3) + (threadIdx.x >> 5);
    int lane = threadIdx.x & 31;
    int d = lane & 15;
    float v = ne[n * DD + d] + te[d];

    float s = v;
    #pragma unroll
    for (int off = 16; off > 0; off >>= 1) s += __shfl_xor_sync(0xffffffffu, s, off);
    float mean = s * (1.0f / 32.0f);
    float dv = v - mean;
    float q = dv * dv;
    #pragma unroll
    for (int off = 16; off > 0; off >>= 1) q += __shfl_xor_sync(0xffffffffu, q, off);
    float var = q * (1.0f / 32.0f);
    float inv = rsqrtf(var + 1e-12f);

    float eg = dv * inv * gw[d] + gbln[d];
    float eu = dv * inv * uw[d] + ubln[d];
    if (lane < 16) { g_eg[n * DD + d] = eg; g_eu[n * DD + d] = eu; }

    for (int o = lane; o < 128; o += 32) {
        float b = 0.f;
        #pragma unroll
        for (int dd = 0; dd < 16; dd++)
            b += __shfl_sync(0xffffffffu, eg, dd) * gate_b[dd * 128 + o];
        g_bg[n * 128 + o] = b;
    }
    for (int o = lane; o < 64; o += 32) {
        float b = 0.f;
        #pragma unroll
        for (int dd = 0; dd < 16; dd++)
            b += __shfl_sync(0xffffffffu, eu, dd) * update_b[dd * 64 + o];
        g_bu[n * 64 + o] = b;
    }
}

// ---------------- 2) S = softmax(e e^T), fp16; 16 rows/block, 512 threads ----------------
#define SUP_STRIDE 1032
#define SUP_SMEM (16 * SUP_STRIDE * 4)

__global__ void __launch_bounds__(512)
k_supports()
{
    extern __shared__ float eT[];
    const int which = blockIdx.y;
    const float* e = which ? g_eu : g_eg;
    unsigned short* Sh = which ? g_Suh : g_Sgh;
    const int tid = threadIdx.x;
    const int warp = tid >> 5, lane = tid & 31;
    const int n = (blockIdx.x << 4) + warp;

    #pragma unroll
    for (int i = 0; i < 32; i++) {
        int idx = tid + (i << 9);
        int m = idx >> 4, dd = idx & 15;
        eT[dd * SUP_STRIDE + m] = e[idx];
    }
    __syncthreads();

    float en[16];
    #pragma unroll
    for (int dd = 0; dd < 16; dd++) en[dd] = eT[dd * SUP_STRIDE + n];

    float lv[32];
    float mx = -1e30f;
    #pragma unroll
    for (int j = 0; j < 8; j++) {
        int m0 = (j << 7) + (lane << 2);
        float ax = 0.f, ay = 0.f, az = 0.f, aw = 0.f;
        #pragma unroll
        for (int dd = 0; dd < 16; dd++) {
            float4 v = *(const float4*)&eT[dd * SUP_STRIDE + m0];
            ax += en[dd] * v.x; ay += en[dd] * v.y;
            az += en[dd] * v.z; aw += en[dd] * v.w;
        }
        lv[j * 4 + 0] = ax; lv[j * 4 + 1] = ay;
        lv[j * 4 + 2] = az; lv[j * 4 + 3] = aw;
        mx = fmaxf(mx, fmaxf(fmaxf(ax, ay), fmaxf(az, aw)));
    }
    #pragma unroll
    for (int off = 16; off > 0; off >>= 1)
        mx = fmaxf(mx, __shfl_xor_sync(0xffffffffu, mx, off));

    float sum = 0.f;
    #pragma unroll
    for (int i = 0; i < 32; i++) { lv[i] = expf(lv[i] - mx); sum += lv[i]; }
    #pragma unroll
    for (int off = 16; off > 0; off >>= 1)
        sum += __shfl_xor_sync(0xffffffffu, sum, off);
    float invs = 1.0f / sum;

    #pragma unroll
    for (int j = 0; j < 8; j++) {
        int m0 = (j << 7) + (lane << 2);
        __half2 p0 = __floats2half2_rn(lv[j * 4 + 0] * invs, lv[j * 4 + 1] * invs);
        __half2 p1 = __floats2half2_rn(lv[j * 4 + 2] * invs, lv[j * 4 + 3] * invs);
        uint2 pk = { *reinterpret_cast<uint32_t*>(&p0), *reinterpret_cast<uint32_t*>(&p1) };
        *(uint2*)&Sh[n * NN + m0] = pk;
    }
}

// ---------------- 3) tensor-core wgen (combined gate+update) ----------------
__global__ void __launch_bounds__(256)
k_wgen_mma(const float* __restrict__ gate_W, const float* __restrict__ update_W)
{
    const int bx = blockIdx.x;
    const int which = bx >= (KIO_G / 512);
    const int KIO = which ? KIO_U : KIO_G;
    const float* Wp = which ? update_W : gate_W;
    unsigned short* wh = which ? g_wuh : g_wgh;
    const float* e = which ? g_eu : g_eg;
    const int kio0 = (which ? bx - KIO_G / 512 : bx) << 9;
    const int n0 = blockIdx.y << 6;

    __shared__ char sm[16384 + 2048 + 2048];
    const uint32_t su = smem_to_u32(sm);
    const int tid = threadIdx.x;
    const int wid = tid >> 5, lane = tid & 31;

    {
        float4 v = *(const float4*)&e[n0 * DD + tid * 4];
        ushort4 h4, l4;
        f16split(v.x, h4.x, l4.x); f16split(v.y, h4.y, l4.y);
        f16split(v.z, h4.z, l4.z); f16split(v.w, h4.w, l4.w);
        *(ushort4*)(sm + 16384 + tid * 8) = h4;
        *(ushort4*)(sm + 18432 + tid * 8) = l4;
    }
    #pragma unroll
    for (int i = 0; i < 8; i++) {
        int lin = tid + (i << 8);
        int r = lin >> 7;
        int cf4 = lin & 127;
        float4 v = *(const float4*)&Wp[(size_t)r * KIO + kio0 + cf4 * 4];
        __half2 p0 = __floats2half2_rn(v.x, v.y);
        __half2 p1 = __floats2half2_rn(v.z, v.w);
        uint2 pk = { *reinterpret_cast<uint32_t*>(&p0), *reinterpret_cast<uint32_t*>(&p1) };
        uint32_t cb = (uint32_t)(cf4 * 8);
        *(uint2*)(sm + r * 1024 + (cb ^ ((r & 7) << 4))) = pk;
    }
    __syncthreads();

    const int mw = wid & 3;
    const int nhalf = wid >> 2;
    const int g = lane >> 2, t4 = lane & 3;

    uint32_t a_h[4], a_l[4];
    {
        uint32_t ao = (uint32_t)((mw * 16 + (lane & 15)) * 32 + ((lane >> 4) << 4));
        ldsm_x4(a_h[0], a_h[1], a_h[2], a_h[3], su + 16384 + ao);
        ldsm_x4(a_l[0], a_l[1], a_l[2], a_l[3], su + 18432 + ao);
    }

    const int brow = (lane & 7) + (((lane >> 3) & 1) << 3);
    const uint32_t bxor = (uint32_t)((brow & 7) << 4);
    const uint32_t bgrp = (uint32_t)((lane >> 4) << 4);

    #pragma unroll
    for (int nt2 = 0; nt2 < 16; nt2++) {
        uint32_t b[2][2];
        uint32_t bo = (uint32_t)(brow * 1024) + ((uint32_t)(nhalf * 512 + nt2 * 32 + bgrp) ^ bxor);
        ldsm_x4_t(b[0][0], b[0][1], b[1][0], b[1][1], su + bo);
        #pragma unroll
        for (int t = 0; t < 2; t++) {
            float c[4] = {0.f, 0.f, 0.f, 0.f};
            mma16816(c, a_h, b[t]);
            mma16816(c, a_l, b[t]);
            int node = n0 + mw * 16 + g;
            int kio = kio0 + nhalf * 256 + nt2 * 16 + t * 8 + 2 * t4;
            __half2 p0 = __floats2half2_rn(c[0], c[1]);
            __half2 p1 = __floats2half2_rn(c[2], c[3]);
            *(uint32_t*)(wh + (size_t)node * KIO + kio)       = *reinterpret_cast<uint32_t*>(&p0);
            *(uint32_t*)(wh + (size_t)(node + 8) * KIO + kio) = *reinterpret_cast<uint32_t*>(&p1);
        }
    }
}

// ---------------- 4) build X0 = fp16(concat(x, state)) ----------------
__global__ void k_build_xin(const float* __restrict__ x, const float* __restrict__ state)
{
    int t = blockIdx.x * 256 + threadIdx.x;
    int n = t >> 11;
    int j = t & 2047;
    int b = j >> 5;
    int c = (j & 31) << 2;

    float4 v;
    if (c < 64) {
        v = *(const float4*)&x[b * (NN * CC) + n * CC + c];
    } else {
        v = *(const float4*)&state[b * (NN * HH) + n * HH + (c - 64)];
    }
    __half2 p0 = __floats2half2_rn(v.x, v.y);
    __half2 p1 = __floats2half2_rn(v.z, v.w);
    uint2 pk = { *reinterpret_cast<uint32_t*>(&p0), *reinterpret_cast<uint32_t*>(&p1) };
    *(uint2*)&g_X0h[n * BC + b * CIN + c] = pk;
}

// ---------------- 4c) T2 = 2*S@S - I (fp16); 64x128 tiles, B via trans-ldmatrix ----------------
#define SS_STAGE 24576
#define SS_SMEM  49152

__global__ void __launch_bounds__(256, 4)
k_ss()
{
    extern __shared__ char smem[];
    const uint32_t smem_u = smem_to_u32(smem);
    const unsigned short* Sh = blockIdx.z ? g_Suh : g_Sgh;
    unsigned short* T2 = blockIdx.z ? g_T2u : g_T2g;

    const int tid = threadIdx.x;
    const int wid = tid >> 5, lane = tid & 31;
    const int brow = blockIdx.y << 6;
    const int bcol = blockIdx.x << 7;
    const int wm = wid & 1, wn = wid >> 1;

    float acc[2][4][4];
    #pragma unroll
    for (int i = 0; i < 2; i++)
        #pragma unroll
        for (int j = 0; j < 4; j++)
            #pragma unroll
            for (int q = 0; q < 4; q++) acc[i][j][q] = 0.f;

    const int arow = wm * 32 + (lane & 15);
    const int axor = (arow & 7) << 4;
    const int agco = (lane >> 4) << 4;
    const int bkrow = (lane & 7) + (((lane >> 3) & 1) << 3);
    const uint32_t bxor2 = (uint32_t)((lane & 7) << 4);
    const uint32_t bgrp = (uint32_t)((lane >> 4) << 4);

    auto load_stage = [&](int buf, int kk) {
        uint32_t dst0 = smem_u + buf * SS_STAGE;
        #pragma unroll
        for (int i = 0; i < 6; i++) {
            int lin = tid + (i << 8);
            if (lin < 512) {
                int r = lin >> 3;
                int cb = (lin & 7) << 4;
                const char* src = (const char*)(Sh + (size_t)(brow + r) * NN + kk) + cb;
                CP_ASYNC16(dst0 + r * 128 + (cb ^ ((r & 7) << 4)), src);
            } else {
                int idx = lin - 512;
                int kr = idx >> 4;
                int cb = (idx & 15) << 4;
                const char* src = (const char*)(Sh + (size_t)(kk + kr) * NN + bcol) + cb;
                CP_ASYNC16(dst0 + 8192 + kr * 256 + (cb ^ ((kr & 7) << 4)), src);
            }
        }
        CP_COMMIT();
    };

    load_stage(0, 0);

    #pragma unroll 1
    for (int s = 0; s < 16; s++) {
        const int buf = s & 1;
        CP_WAIT0();
        __syncthreads();
        if (s + 1 < 16) load_stage(1 - buf, (s + 1) << 6);

        const uint32_t sb = smem_u + buf * SS_STAGE;
        #pragma unroll
        for (int ks = 0; ks < 4; ks++) {
            const int c = ks << 5;
            uint32_t ah[2][4], bh[4][2];
            #pragma unroll
            for (int mt = 0; mt < 2; mt++) {
                uint32_t ao = (uint32_t)((arow + mt * 16) * 128) + (uint32_t)((c + agco) ^ axor);
                ldsm_x4(ah[mt][0], ah[mt][1], ah[mt][2], ah[mt][3], sb + ao);
            }
            #pragma unroll
            for (int nb = 0; nb < 2; nb++) {
                uint32_t bo = (uint32_t)((ks * 16 + bkrow) * 256)
                            + ((uint32_t)(wn * 64 + nb * 32 + bgrp) ^ bxor2);
                ldsm_x4_t(bh[2 * nb][0], bh[2 * nb][1], bh[2 * nb + 1][0], bh[2 * nb + 1][1],
                          sb + 8192 + bo);
            }
            #pragma unroll
            for (int mt = 0; mt < 2; mt++)
                #pragma unroll
                for (int nt = 0; nt < 4; nt++)
                    mma16816(acc[mt][nt], ah[mt], bh[nt]);
        }
        __syncthreads();
    }

    const int g = lane >> 2, t4 = lane & 3;
    #pragma unroll
    for (int mt = 0; mt < 2; mt++) {
        #pragma unroll
        for (int nt = 0; nt < 4; nt++) {
            int m0 = wm * 32 + mt * 16 + g;
            int n0c = wn * 32 + nt * 8 + 2 * t4;
            #pragma unroll
            for (int half = 0; half < 2; half++) {
                int m = m0 + half * 8;
                int row = brow + m, col = bcol + n0c;
                float v0 = 2.0f * acc[mt][nt][2 * half]     - (row == col ? 1.0f : 0.0f);
                float v1 = 2.0f * acc[mt][nt][2 * half + 1] - (row == col + 1 ? 1.0f : 0.0f);
                __half2 p = __floats2half2_rn(v0, v1);
                *(uint32_t*)(T2 + (size_t)row * NN + col) = *reinterpret_cast<uint32_t*>(&p);
            }
        }
    }
}

// ---------------- 5) fused big GEMM: [Y1;Y2] = [S;T2] @ X0 -> fp16 out ----------------
#define STAGE_BYTES 32768
#define TCG_SMEM 65536

__global__ void __launch_bounds__(256, 2)
k_mmagemm2(const unsigned short* __restrict__ A1,
           const unsigned short* __restrict__ A2,
           const unsigned short* __restrict__ Bx,
           unsigned short* __restrict__ O1h, unsigned short* __restrict__ O2h)
{
    extern __shared__ char smem[];
    const uint32_t smem_u = smem_to_u32(smem);
    const int tid = threadIdx.x;
    const int wid = tid >> 5;
    const int lane = tid & 31;
    const int by = blockIdx.y;
    const int rowA = (by & 7) << 7;
    const int bcol = blockIdx.x << 7;
    const int wm = wid & 1;
    const int wn = wid >> 1;

    const unsigned short* Aarr = (by < 8) ? A1 : A2;
    unsigned short* Xh = (by < 8) ? O1h : O2h;

    float acc[4][4][4];
    #pragma unroll
    for (int i = 0; i < 4; i++)
        #pragma unroll
        for (int j = 0; j < 4; j++)
            #pragma unroll
            for (int q = 0; q < 4; q++) acc[i][j][q] = 0.f;

    const int arow = wm * 64 + (lane & 15);
    const int axor = (arow & 7) << 4;
    const int agco = (lane >> 4) << 4;
    const int bkrow = (lane & 7) + (((lane >> 3) & 1) << 3);
    const uint32_t bxor2 = (uint32_t)((lane & 7) << 4);
    const uint32_t bgrp = (uint32_t)((lane >> 4) << 4);

    auto load_stage = [&](int buf, int kk) {
        uint32_t dst0 = smem_u + buf * STAGE_BYTES;
        #pragma unroll
        for (int i = 0; i < 8; i++) {
            int lin = tid + (i << 8);
            if (lin < 1024) {
                int r = lin >> 3;
                int cb = (lin & 7) << 4;
                const char* src = (const char*)(Aarr + (size_t)(rowA + r) * NN + kk) + cb;
                CP_ASYNC16(dst0 + r * 128 + (cb ^ ((r & 7) << 4)), src);
            } else {
                int idx = lin - 1024;
                int kr = idx >> 4;
                int cb = (idx & 15) << 4;
                const char* src = (const char*)(Bx + (size_t)(kk + kr) * BC + bcol) + cb;
                CP_ASYNC16(dst0 + 16384 + kr * 256 + (cb ^ ((kr & 7) << 4)), src);
            }
        }
        CP_COMMIT();
    };

    load_stage(0, 0);

    #pragma unroll 1
    for (int s = 0; s < 16; s++) {
        const int buf = s & 1;
        CP_WAIT0();
        __syncthreads();
        if (s + 1 < 16) load_stage(1 - buf, (s + 1) << 6);

        const uint32_t sb = smem_u + buf * STAGE_BYTES;
        #pragma unroll
        for (int ks = 0; ks < 4; ks++) {
            const int c = ks << 5;
            uint32_t ah[4][4], bh[4][2];
            #pragma unroll
            for (int mt = 0; mt < 4; mt++) {
                uint32_t ao = (uint32_t)((arow + mt * 16) * 128) + (uint32_t)((c + agco) ^ axor);
                ldsm_x4(ah[mt][0], ah[mt][1], ah[mt][2], ah[mt][3], sb + ao);
            }
            #pragma unroll
            for (int nb = 0; nb < 2; nb++) {
                uint32_t bo = (uint32_t)((ks * 16 + bkrow) * 256)
                            + ((uint32_t)(wn * 64 + nb * 32 + bgrp) ^ bxor2);
                ldsm_x4_t(bh[2 * nb][0], bh[2 * nb][1], bh[2 * nb + 1][0], bh[2 * nb + 1][1],
                          sb + 16384 + bo);
            }
            #pragma unroll
            for (int mt = 0; mt < 4; mt++)
                #pragma unroll
                for (int nt = 0; nt < 4; nt++)
                    mma16816(acc[mt][nt], ah[mt], bh[nt]);
        }
        __syncthreads();
    }

    const int g = lane >> 2, t4 = lane & 3;
    #pragma unroll
    for (int mt = 0; mt < 4; mt++) {
        #pragma unroll
        for (int nt = 0; nt < 4; nt++) {
            int m0 = wm * 64 + mt * 16 + g;
            int n0c = wn * 32 + nt * 8 + 2 * t4;
            #pragma unroll
            for (int half = 0; half < 2; half++) {
                int m = m0 + half * 8;
                __half2 p = __floats2half2_rn(acc[mt][nt][2 * half], acc[mt][nt][2 * half + 1]);
                *(uint32_t*)(Xh + (size_t)(rowA + m) * BC + bcol + n0c) =
                    *reinterpret_cast<uint32_t*>(&p);
            }
        }
    }
}

// ---------------- 6) node GEMM gate (1-term, double-buffered) ----------------
#define GATE_STAGE 24576
#define GATE_SMEM 49152

__global__ void __launch_bounds__(256)
k_tc_gate(const float* __restrict__ state)
{
    extern __shared__ char sm[];
    const uint32_t su = smem_to_u32(sm);
    const int n = blockIdx.x;
    const int tid = threadIdx.x;
    const int wid = tid >> 5, lane = tid & 31;
    const int wm = wid & 1, wn = wid >> 1;

    const unsigned short* xh[3] = { g_X0h + (size_t)n * BC, g_X1h + (size_t)n * BC, g_X2h + (size_t)n * BC };
    const unsigned short* wh = g_wgh + (size_t)n * KIO_G;

    float acc[2][4][4];
    #pragma unroll
    for (int i = 0; i < 2; i++)
        #pragma unroll
        for (int j = 0; j < 4; j++)
            #pragma unroll
            for (int q = 0; q < 4; q++) acc[i][j][q] = 0.f;

    const int arow = wm * 32 + (lane & 15);
    const int axor = (arow & 7) << 4;
    const int agco = (lane >> 4) << 4;
    const int brow = (lane & 7) + (((lane >> 3) & 1) << 3);
    const int bxor = (lane & 7) << 4;
    const int bgrp = (lane >> 4) << 4;

    auto load_stage = [&](int buf, int q) {
        const int t = q >> 1;
        const int c0 = (q & 1) << 6;
        uint32_t b0 = su + buf * GATE_STAGE;
        #pragma unroll
        for (int i = 0; i < 2; i++) {
            int lin = tid + (i << 8);
            int r = lin >> 3;
            int cb = (lin & 7) << 4;
            CP_ASYNC16(b0 + r * 128 + (cb ^ ((r & 7) << 4)),
                       (const char*)(xh[t] + r * 128 + c0) + cb);
        }
        #pragma unroll
        for (int i = 0; i < 4; i++) {
            int lin = tid + (i << 8);
            int kr = lin >> 4;
            int cb = (lin & 15) << 4;
            CP_ASYNC16(b0 + 8192 + kr * 256 + (cb ^ ((kr & 7) << 4)),
                       (const char*)(wh + (size_t)(q * 64 + kr) * 128) + cb);
        }
        CP_COMMIT();
    };

    load_stage(0, 0);

    #pragma unroll 1
    for (int q = 0; q < 6; q++) {
        const int buf = q & 1;
        if (q + 1 < 6) { load_stage(1 - buf, q + 1); CP_WAIT1(); }
        else           { CP_WAIT0(); }
        __syncthreads();

        const uint32_t sb = su + buf * GATE_STAGE;
        #pragma unroll
        for (int ks = 0; ks < 4; ks++) {
            const int c = ks << 5;
            uint32_t ah[2][4], bh[4][2];
            #pragma unroll
            for (int mt = 0; mt < 2; mt++) {
                uint32_t ao = (uint32_t)((arow + mt * 16) * 128) + (uint32_t)((c + agco) ^ axor);
                ldsm_x4(ah[mt][0], ah[mt][1], ah[mt][2], ah[mt][3], sb + ao);
            }
            #pragma unroll
            for (int nb = 0; nb < 2; nb++) {
                uint32_t bo = (uint32_t)((ks * 16 + brow) * 256)
                            + (uint32_t)((wn * 64 + nb * 32 + bgrp) ^ bxor);
                ldsm_x4_t(bh[2 * nb][0], bh[2 * nb][1], bh[2 * nb + 1][0], bh[2 * nb + 1][1],
                          sb + 8192 + bo);
            }
            #pragma unroll
            for (int mt = 0; mt < 2; mt++)
                #pragma unroll
                for (int nt = 0; nt < 4; nt++)
                    mma16816(acc[mt][nt], ah[mt], bh[nt]);
        }
        __syncthreads();
    }

    const int g = lane >> 2, t4 = lane & 3;
    #pragma unroll
    for (int mt = 0; mt < 2; mt++) {
        int b0 = wm * 32 + mt * 16 + g;
        #pragma unroll
        for (int nt = 0; nt < 4; nt++) {
            int o = wn * 32 + nt * 8 + 2 * t4;
            float bi0 = g_bg[n * 128 + o];
            float bi1 = g_bg[n * 128 + o + 1];
            #pragma unroll
            for (int half = 0; half < 2; half++) {
                int b = b0 + half * 8;
                float v0 = acc[mt][nt][2 * half]     + bi0;
                float v1 = acc[mt][nt][2 * half + 1] + bi1;
                float s0 = 1.0f / (1.0f + expf(-v0));
                float s1 = 1.0f / (1.0f + expf(-v1));
                if (o < 64) {
                    int sidx = b * (NN * HH) + n * HH + o;
                    __half2 p = __floats2half2_rn(s0 * state[sidx], s1 * state[sidx + 1]);
                    *(uint32_t*)&g_X0h[n * BC + b * CIN + 64 + o] =
                        *reinterpret_cast<uint32_t*>(&p);
                } else {
                    int base = b * (NN * HH) + n * HH + (o - 64);
                    g_r[base] = s0; g_r[base + 1] = s1;
                }
            }
        }
    }
}

// ---------------- 7) node GEMM update (1-term, double-buffered) ----------------
#define UPD_STAGE 16384

__global__ void __launch_bounds__(128)
k_tc_upd(const float* __restrict__ state, float* __restrict__ dout)
{
    __shared__ char sm[2 * UPD_STAGE];
    const uint32_t su = smem_to_u32(sm);
    const int n = blockIdx.x;
    const int tid = threadIdx.x;
    const int wid = tid >> 5, lane = tid & 31;
    const int wm = wid & 1, wn = wid >> 1;

    const unsigned short* xh[3] = { g_X0h + (size_t)n * BC, g_X1h + (size_t)n * BC, g_X2h + (size_t)n * BC };
    const unsigned short* wh = g_wuh + (size_t)n * KIO_U;

    float acc[2][4][4];
    #pragma unroll
    for (int i = 0; i < 2; i++)
        #pragma unroll
        for (int j = 0; j < 4; j++)
            #pragma unroll
            for (int q = 0; q < 4; q++) acc[i][j][q] = 0.f;

    const int arow = wm * 32 + (lane & 15);
    const int axor = (arow & 7) << 4;
    const int agco = (lane >> 4) << 4;
    const int brow = (lane & 7) + (((lane >> 3) & 1) << 3);
    const int bxor = (lane & 7) << 4;
    const int bgrp = (lane >> 4) << 4;

    auto load_stage = [&](int buf, int q) {
        const int t = q >> 1;
        const int c0 = (q & 1) << 6;
        uint32_t b0 = su + buf * UPD_STAGE;
        #pragma unroll
        for (int i = 0; i < 4; i++) {
            int lin = tid + (i << 7);
            int r = lin >> 3;
            int cb = (lin & 7) << 4;
            CP_ASYNC16(b0 + r * 128 + (cb ^ ((r & 7) << 4)),
                       (const char*)(xh[t] + r * 128 + c0) + cb);
        }
        #pragma unroll
        for (int i = 0; i < 4; i++) {
            int lin = tid + (i << 7);
            int kr = lin >> 3;
            int cb = (lin & 7) << 4;
            CP_ASYNC16(b0 + 8192 + kr * 128 + (cb ^ ((kr & 7) << 4)),
                       (const char*)(wh + (size_t)(q * 64 + kr) * 64) + cb);
        }
        CP_COMMIT();
    };

    load_stage(0, 0);

    #pragma unroll 1
    for (int q = 0; q < 6; q++) {
        const int buf = q & 1;
        if (q + 1 < 6) { load_stage(1 - buf, q + 1); CP_WAIT1(); }
        else           { CP_WAIT0(); }
        __syncthreads();

        const uint32_t sb = su + buf * UPD_STAGE;
        #pragma unroll
        for (int ks = 0; ks < 4; ks++) {
            const int c = ks << 5;
            uint32_t ah[2][4], bh[4][2];
            #pragma unroll
            for (int mt = 0; mt < 2; mt++) {
                uint32_t ao = (uint32_t)((arow + mt * 16) * 128) + (uint32_t)((c + agco) ^ axor);
                ldsm_x4(ah[mt][0], ah[mt][1], ah[mt][2], ah[mt][3], sb + ao);
            }
            #pragma unroll
            for (int nb = 0; nb < 2; nb++) {
                uint32_t bo = (uint32_t)((ks * 16 + brow) * 128)
                            + (uint32_t)((wn * 64 + nb * 32 + bgrp) ^ bxor);
                ldsm_x4_t(bh[2 * nb][0], bh[2 * nb][1], bh[2 * nb + 1][0], bh[2 * nb + 1][1],
                          sb + 8192 + bo);
            }
            #pragma unroll
            for (int mt = 0; mt < 2; mt++)
                #pragma unroll
                for (int nt = 0; nt < 4; nt++)
                    mma16816(acc[mt][nt], ah[mt], bh[nt]);
        }
        __syncthreads();
    }

    const int g = lane >> 2, t4 = lane & 3;
    #pragma unroll
    for (int mt = 0; mt < 2; mt++) {
        int b0 = wm * 32 + mt * 16 + g;
        #pragma unroll
        for (int nt = 0; nt < 4; nt++) {
            int o = wn * 32 + nt * 8 + 2 * t4;
            float bi0 = g_bu[n * 64 + o];
            float bi1 = g_bu[n * 64 + o + 1];
            #pragma unroll
            for (int half = 0; half < 2; half++) {
                int b = b0 + half * 8;
                float hc0 = tanhf(acc[mt][nt][2 * half]     + bi0);
                float hc1 = tanhf(acc[mt][nt][2 * half + 1] + bi1);
                int idx = b * (NN * HH) + n * HH + o;
                float r0 = g_r[idx],     st0 = state[idx];
                float r1 = g_r[idx + 1], st1 = state[idx + 1];
                dout[idx]     = r0 * st0 + (1.0f - r0) * hc0;
                dout[idx + 1] = r1 * st1 + (1.0f - r1) * hc1;
            }
        }
    }
}

// ---------------- launch ----------------
extern "C" void kernel_launch(void* const* d_in, const int* in_sizes, int n_in,
                              void* d_out, int out_size)
{
    const float* x         = (const float*)d_in[0];
    const float* state     = (const float*)d_in[2];
    const float* node_emb  = (const float*)d_in[3];
    const float* time_emb  = (const float*)d_in[5];
    const float* gate_W    = (const float*)d_in[6];
    const float* gate_b    = (const float*)d_in[7];
    const float* gate_lnw  = (const float*)d_in[8];
    const float* gate_lnb  = (const float*)d_in[9];
    const float* update_W  = (const float*)d_in[10];
    const float* update_b  = (const float*)d_in[11];
    const float* update_lnw= (const float*)d_in[12];
    const float* update_lnb= (const float*)d_in[13];
    float* out = (float*)d_out;

    unsigned short *Sgh, *Suh, *T2g, *T2u, *X0h, *X1h, *X2h;
    cudaGetSymbolAddress((void**)&Sgh, g_Sgh);
    cudaGetSymbolAddress((void**)&Suh, g_Suh);
    cudaGetSymbolAddress((void**)&T2g, g_T2g);
    cudaGetSymbolAddress((void**)&T2u, g_T2u);
    cudaGetSymbolAddress((void**)&X0h, g_X0h);
    cudaGetSymbolAddress((void**)&X1h, g_X1h);
    cudaGetSymbolAddress((void**)&X2h, g_X2h);

    static cudaStream_t sB = nullptr, sW = nullptr;
    static cudaEvent_t evRoot = nullptr, evPrep = nullptr, evB = nullptr, evW = nullptr;
    if (!sB) {
        cudaStreamCreateWithFlags(&sB, cudaStreamNonBlocking);
        cudaStreamCreateWithFlags(&sW, cudaStreamNonBlocking);
        cudaEventCreateWithFlags(&evRoot, cudaEventDisableTiming);
        cudaEventCreateWithFlags(&evPrep, cudaEventDisableTiming);
        cudaEventCreateWithFlags(&evB, cudaEventDisableTiming);
        cudaEventCreateWithFlags(&evW, cudaEventDisableTiming);
        cudaFuncSetAttribute(k_mmagemm2, cudaFuncAttributeMaxDynamicSharedMemorySize, TCG_SMEM);
        cudaFuncSetAttribute(k_ss, cudaFuncAttributeMaxDynamicSharedMemorySize, SS_SMEM);
        cudaFuncSetAttribute(k_tc_gate, cudaFuncAttributeMaxDynamicSharedMemorySize, GATE_SMEM);
        cudaFuncSetAttribute(k_supports, cudaFuncAttributeMaxDynamicSharedMemorySize, SUP_SMEM);
    }

    cudaEventRecord(evRoot, 0);

    // branch B: build X0 (no deps)
    cudaStreamWaitEvent(sB, evRoot, 0);
    k_build_xin<<<(NN * BC / 4) / 256, 256, 0, sB>>>(x, state);
    cudaEventRecord(evB, sB);

    // main: prep (8 warps/block)
    k_prep<<<NN / 8, 256>>>(node_emb, time_emb, gate_lnw, gate_lnb, update_lnw, update_lnb,
                            gate_b, update_b);
    cudaEventRecord(evPrep, 0);

    // branch W: per-node weights (needs e)
    cudaStreamWaitEvent(sW, evPrep, 0);
    k_wgen_mma<<<dim3(KIO_G / 512 + KIO_U / 512, NN / 64), 256, 0, sW>>>(gate_W, update_W);
    cudaEventRecord(evW, sW);

    // main: supports -> T2
    k_supports<<<dim3(NN / 16, 2), 512, SUP_SMEM>>>();
    k_ss<<<dim3(8, 16, 2), 256, SS_SMEM>>>();

    dim3 gg2(BC / 128, 16);

    // ---- gate magcn ----
    cudaStreamWaitEvent(0, evB, 0);
    k_mmagemm2<<<gg2, 256, TCG_SMEM>>>(Sgh, T2g, X0h, X1h, X2h);
    cudaStreamWaitEvent(0, evW, 0);
    k_tc_gate<<<NN, 256, GATE_SMEM>>>(state);   // z*state -> X0 state-half; r -> g_r

    // ---- update magcn ----
    k_mmagemm2<<<gg2, 256, TCG_SMEM>>>(Suh, T2u, X0h, X1h, X2h);
    k_tc_upd<<<NN, 128>>>(state, out);
}